// round 10
// baseline (speedup 1.0000x reference)
#include <cuda_runtime.h>
#include <cuda_bf16.h>
#include <cstdint>

// Problem constants
#define Bn 512
#define Tn 512
#define En 64
#define Hn 64
#define Gn 256   // 4*H
#define Cn 8
#define Rr 2     // batch rows per LSTM block
#define PF 4     // xw prefetch depth (steps)
#define GROWS 128 // rows per GEMM block

typedef unsigned long long u64;

// Scratch (device globals: no cudaMalloc allowed)
__device__ float g_bufA[Bn * Tn * En];
__device__ float g_bufB[Bn * Tn * Hn];
__device__ float g_xw[Bn * Tn * Gn];

// ---------------------------------------------------------------------------
// packed f32x2 helpers
// ---------------------------------------------------------------------------
__device__ __forceinline__ u64 pack2(float lo, float hi) {
    u64 r; asm("mov.b64 %0, {%1, %2};" : "=l"(r) : "f"(lo), "f"(hi)); return r;
}
__device__ __forceinline__ void unpack2(u64 v, float& lo, float& hi) {
    asm("mov.b64 {%0, %1}, %2;" : "=f"(lo), "=f"(hi) : "l"(v));
}
__device__ __forceinline__ u64 fma2(u64 a, u64 b, u64 c) {
    u64 d; asm("fma.rn.f32x2 %0, %1, %2, %3;" : "=l"(d) : "l"(a), "l"(b), "l"(c));
    return d;
}
__device__ __forceinline__ float hsum4(u64 a, u64 b) {
    float p, q, s, t;
    unpack2(a, p, q); unpack2(b, s, t);
    return (p + q) + (s + t);
}

__device__ __forceinline__ float sigf(float x) {
    return 1.f / (1.f + __expf(-x));
}
__device__ __forceinline__ float tanhfast(float x) {
    return 2.f / (1.f + __expf(-2.f * x)) - 1.f;
}

// ---------------------------------------------------------------------------
// Embedding
// ---------------------------------------------------------------------------
__global__ void embed_kernel(const int* __restrict__ ids,
                             const float* __restrict__ wt,
                             const float* __restrict__ pt,
                             float* __restrict__ out)
{
    int i = blockIdx.x * blockDim.x + threadIdx.x;
    int bt = i >> 4;
    int v  = i & 15;
    int id = ids[bt];
    int t  = bt & (Tn - 1);
    float4 a = ((const float4*)wt)[id * 16 + v];
    float4 p = ((const float4*)pt)[t * 16 + v];
    float4 r;
    r.x = a.x + p.x; r.y = a.y + p.y; r.z = a.z + p.z; r.w = a.w + p.w;
    ((float4*)out)[i] = r;
}

// ---------------------------------------------------------------------------
// XW GEMM with split-K thread pairs:
// thread (kh = tid&1, jj = tid>>1) computes columns (jj, jj+128) over
// k in [kh*32, kh*32+32). One LDS.128 feeds 4 FFMA2. Partials combined
// via shfl_xor(1); thread stores its own column (kh=0 -> jj, kh=1 -> jj+128).
// Weight regs: 32 u64 (64 regs) -> 2 blocks/SM retained.
// ---------------------------------------------------------------------------
__global__ void __launch_bounds__(256, 2)
gemm_xw_kernel(const float* __restrict__ X,
               const float* __restrict__ Wx,
               const float* __restrict__ bias,
               float* __restrict__ XW)
{
    const int tid  = threadIdx.x;
    const int kh   = tid & 1;
    const int jj   = tid >> 1;          // 0..127
    const int kb   = kh * 32;           // k-half base
    const int myc  = jj + 128 * kh;     // column this thread finalizes
    const int rowB = blockIdx.x * GROWS;

    __shared__ __align__(16) float xs[GROWS * 64];   // 32 KB

    // weight pairs for columns jj and jj+128, k-half kb
    u64 wp0[16], wp1[16];
#pragma unroll
    for (int m = 0; m < 16; m++) {
        wp0[m] = pack2(Wx[(kb + 2*m) * Gn + jj],       Wx[(kb + 2*m + 1) * Gn + jj]);
        wp1[m] = pack2(Wx[(kb + 2*m) * Gn + jj + 128], Wx[(kb + 2*m + 1) * Gn + jj + 128]);
    }
    const float bmy = bias[myc];

    // cooperative tile load GROWS x 64 floats
    const float4* Xv = (const float4*)(X + (size_t)rowB * En);
    float4* xs4 = (float4*)xs;
#pragma unroll
    for (int i = 0; i < (GROWS * 16) / 256; i++)
        xs4[tid + i * 256] = Xv[tid + i * 256];
    __syncthreads();

    float* outp = XW + (size_t)rowB * Gn + myc;
#pragma unroll 2
    for (int r = 0; r < GROWS; r++) {
        const ulonglong2* xr = (const ulonglong2*)&xs[r * 64 + kb];
        u64 a0 = 0ull, a1 = 0ull, d0 = 0ull, d1 = 0ull;
#pragma unroll
        for (int kv = 0; kv < 8; kv++) {
            ulonglong2 v = xr[kv];
            a0 = fma2(wp0[2 * kv],     v.x, a0);
            a1 = fma2(wp0[2 * kv + 1], v.y, a1);
            d0 = fma2(wp1[2 * kv],     v.x, d0);
            d1 = fma2(wp1[2 * kv + 1], v.y, d1);
        }
        float s0 = hsum4(a0, a1);                 // partial for col jj
        float s1 = hsum4(d0, d1);                 // partial for col jj+128
        s0 += __shfl_xor_sync(0xFFFFFFFFu, s0, 1);
        s1 += __shfl_xor_sync(0xFFFFFFFFu, s1, 1);
        outp[(size_t)r * Gn] = (kh ? s1 : s0) + bmy;
    }
}

// ---------------------------------------------------------------------------
// LSTM recurrence, split-K thread pairs in the dot phase.
// Rr=2 rows/block, grid 256 blocks, 2 blocks/SM.
// Gate phase unchanged: threads with (j & 64)==0, row = j>>7, hh = j&63.
// ---------------------------------------------------------------------------
#define LSTM_STEP(T, RING)                                                    \
{                                                                             \
    u64 a0[Rr], a1[Rr], d0[Rr], d1[Rr];                                       \
    _Pragma("unroll")                                                         \
    for (int r = 0; r < Rr; r++) { a0[r]=0ull; a1[r]=0ull; d0[r]=0ull; d1[r]=0ull; } \
    {                                                                         \
        const int tl = (T) + PF;                                              \
        if (tl < Tn) {                                                        \
            _Pragma("unroll")                                                 \
            for (int r = 0; r < Rr; r++)                                      \
                RING[r] = xp[r][(size_t)tl * Gn];                             \
        }                                                                     \
    }                                                                         \
    _Pragma("unroll")                                                         \
    for (int kv = 0; kv < 8; kv++) {                                          \
        const u64 w0 = wp0[2 * kv];                                           \
        const u64 w1 = wp0[2 * kv + 1];                                       \
        const u64 w2 = wp1[2 * kv];                                           \
        const u64 w3 = wp1[2 * kv + 1];                                       \
        _Pragma("unroll")                                                     \
        for (int r = 0; r < Rr; r++) {                                        \
            ulonglong2 hv = *(const ulonglong2*)&hs[r][kb + 4 * kv];          \
            a0[r] = fma2(w0, hv.x, a0[r]);                                    \
            a1[r] = fma2(w1, hv.y, a1[r]);                                    \
            d0[r] = fma2(w2, hv.x, d0[r]);                                    \
            d1[r] = fma2(w3, hv.y, d1[r]);                                    \
        }                                                                     \
    }                                                                         \
    _Pragma("unroll")                                                         \
    for (int r = 0; r < Rr; r++) {                                            \
        float s0 = hsum4(a0[r], a1[r]);                                       \
        float s1 = hsum4(d0[r], d1[r]);                                       \
        s0 += __shfl_xor_sync(0xFFFFFFFFu, s0, 1);                            \
        s1 += __shfl_xor_sync(0xFFFFFFFFu, s1, 1);                            \
        zs[r][myc] = (kh ? s1 : s0) + RING ## _cur[r];                        \
    }                                                                         \
    __syncthreads();                                                          \
    if (gate_active) {                                                        \
        float zi = zs[rp][hh];                                                \
        float zf = zs[rp][64  + hh];                                          \
        float zg = zs[rp][128 + hh];                                          \
        float zo = zs[rp][192 + hh];                                          \
        float ig = sigf(zi);                                                  \
        float fg = sigf(zf);                                                  \
        float gg = tanhfast(zg);                                              \
        float og = sigf(zo);                                                  \
        c = fg * c + ig * gg;                                                 \
        float h = og * tanhfast(c);                                           \
        hs[rp][hh] = h;                                                       \
        hrow[(size_t)(T) * Hn] = h;                                           \
    }                                                                         \
    __syncthreads();                                                          \
}

// helper: the macro needs the pre-refill value of the ring slot; capture it.
#define LSTM_STEP_W(T, RING)                                                  \
{                                                                             \
    float RING ## _cur[Rr];                                                   \
    _Pragma("unroll")                                                         \
    for (int r = 0; r < Rr; r++) RING ## _cur[r] = RING[r];                   \
    LSTM_STEP(T, RING)                                                        \
}

__global__ void __launch_bounds__(256, 2)
lstm_kernel(const float* __restrict__ xw,   // [B*T, 256]
            const float* __restrict__ Wh,   // [64, 256]
            float* __restrict__ hout)       // [B*T, 64]
{
    const int j   = threadIdx.x;
    const int kh  = j & 1;
    const int jj  = j >> 1;              // 0..127
    const int kb  = kh * 32;
    const int myc = jj + 128 * kh;       // column this thread finalizes
    const int b0  = blockIdx.x * Rr;
    const int rp  = j >> 7;              // gate-phase row (0/1)
    const int hh  = j & 63;              // gate-phase hidden index
    const bool gate_active = (j & 64) == 0;

    __shared__ __align__(16) float hs[Rr][Hn];
    __shared__ float zs[Rr][Gn];

    // Wh pairs for columns jj, jj+128 over k-half kb
    u64 wp0[16], wp1[16];
#pragma unroll
    for (int m = 0; m < 16; m++) {
        wp0[m] = pack2(Wh[(kb + 2*m) * Gn + jj],       Wh[(kb + 2*m + 1) * Gn + jj]);
        wp1[m] = pack2(Wh[(kb + 2*m) * Gn + jj + 128], Wh[(kb + 2*m + 1) * Gn + jj + 128]);
    }

    if (j < Rr * Hn) hs[j >> 6][j & 63] = 0.f;
    float c = 0.f;

    // xw stream for this thread's finalized column
    const float* xp[Rr];
#pragma unroll
    for (int r = 0; r < Rr; r++)
        xp[r] = xw + (size_t)(b0 + r) * Tn * Gn + myc;

    // prime the 4-slot ring with t = 0..3
    float ringA[Rr], ringB[Rr], ringC[Rr], ringD[Rr];
#pragma unroll
    for (int r = 0; r < Rr; r++) {
        ringA[r] = xp[r][(size_t)0 * Gn];
        ringB[r] = xp[r][(size_t)1 * Gn];
        ringC[r] = xp[r][(size_t)2 * Gn];
        ringD[r] = xp[r][(size_t)3 * Gn];
    }

    float* hrow = hout + (size_t)(b0 + rp) * Tn * Hn + hh;

    __syncthreads();

    for (int tb = 0; tb < Tn; tb += PF) {
        LSTM_STEP_W(tb + 0, ringA);
        LSTM_STEP_W(tb + 1, ringB);
        LSTM_STEP_W(tb + 2, ringC);
        LSTM_STEP_W(tb + 3, ringD);
    }
}

// ---------------------------------------------------------------------------
// Logits + softmax, duplicated into both time halves (bwd == fwd).
// ---------------------------------------------------------------------------
__global__ void __launch_bounds__(256)
logits_kernel(const float* __restrict__ Hs,
              const float* __restrict__ Wd,
              const float* __restrict__ bd,
              float* __restrict__ out)
{
    __shared__ float wd_s[Hn * Cn];
    __shared__ float bd_s[Cn];
    const int tid = threadIdx.x;
    for (int i = tid; i < Hn * Cn; i += 256) wd_s[i] = Wd[i];
    if (tid < Cn) bd_s[tid] = bd[tid];
    __syncthreads();

    const int row = blockIdx.x * 256 + tid;
    float acc[Cn];
#pragma unroll
    for (int cc = 0; cc < Cn; cc++) acc[cc] = bd_s[cc];

    const float4* hr = (const float4*)(Hs + (size_t)row * Hn);
#pragma unroll
    for (int kv = 0; kv < 16; kv++) {
        float4 x = hr[kv];
#pragma unroll
        for (int cc = 0; cc < Cn; cc++) {
            acc[cc] += x.x * wd_s[(4*kv+0) * Cn + cc];
            acc[cc] += x.y * wd_s[(4*kv+1) * Cn + cc];
            acc[cc] += x.z * wd_s[(4*kv+2) * Cn + cc];
            acc[cc] += x.w * wd_s[(4*kv+3) * Cn + cc];
        }
    }

    float m = acc[0];
#pragma unroll
    for (int cc = 1; cc < Cn; cc++) m = fmaxf(m, acc[cc]);
    float s = 0.f;
    float e[Cn];
#pragma unroll
    for (int cc = 0; cc < Cn; cc++) { e[cc] = __expf(acc[cc] - m); s += e[cc]; }
    float inv = 1.f / s;

    const int b = row >> 9;
    const int t = row & (Tn - 1);
    float4 r0, r1;
    r0.x = e[0]*inv; r0.y = e[1]*inv; r0.z = e[2]*inv; r0.w = e[3]*inv;
    r1.x = e[4]*inv; r1.y = e[5]*inv; r1.z = e[6]*inv; r1.w = e[7]*inv;

    float* o1 = out + ((size_t)b * (2 * Tn) + t) * Cn;
    float* o2 = o1 + (size_t)Tn * Cn;
    ((float4*)o1)[0] = r0; ((float4*)o1)[1] = r1;
    ((float4*)o2)[0] = r0; ((float4*)o2)[1] = r1;
}

// ---------------------------------------------------------------------------
// Launch
// ---------------------------------------------------------------------------
extern "C" void kernel_launch(void* const* d_in, const int* in_sizes, int n_in,
                              void* d_out, int out_size)
{
    const int*   ids        = (const int*)d_in[0];
    const float* word_table = (const float*)d_in[3];
    const float* pos_table  = (const float*)d_in[4];
    const float* Wx         = (const float*)d_in[5];
    const float* Wh         = (const float*)d_in[6];
    const float* b          = (const float*)d_in[7];
    const float* Wd         = (const float*)d_in[8];
    const float* bd         = (const float*)d_in[9];
    float* out = (float*)d_out;

    float *bufA, *bufB, *xwp;
    cudaGetSymbolAddress((void**)&bufA, g_bufA);
    cudaGetSymbolAddress((void**)&bufB, g_bufB);
    cudaGetSymbolAddress((void**)&xwp,  g_xw);

    embed_kernel<<<(Bn * Tn * 16) / 256, 256>>>(ids, word_table, pos_table, bufA);

    gemm_xw_kernel<<<(Bn * Tn) / GROWS, 256>>>(bufA, Wx, b, xwp);
    lstm_kernel<<<Bn / Rr, 256>>>(xwp, Wh, bufB);

    gemm_xw_kernel<<<(Bn * Tn) / GROWS, 256>>>(bufB, Wx, b, xwp);
    lstm_kernel<<<Bn / Rr, 256>>>(xwp, Wh, bufA);

    logits_kernel<<<(Bn * Tn) / 256, 256>>>(bufA, Wd, bd, out);
}